// round 1
// baseline (speedup 1.0000x reference)
#include <cuda_runtime.h>
#include <math.h>

#define T_SEQ 2048
#define HID_DIM 2048
#define NH 16
#define NKV 4
#define HD 128
#define QKV_N ((NH + 2 * NKV) * HD)   // 3072
#define CTX_N (NH * HD)               // 2048

// Scratch (no cudaMalloc allowed): qkv projections and attention context.
__device__ float g_qkv[T_SEQ * QKV_N];   // 25 MB
__device__ float g_ctx[T_SEQ * CTX_N];   // 16 MB

// ---------------------------------------------------------------------------
// Generic fp32 SGEMM: C[M,N] = A[M,Kd] @ B[Kd,N], row-major, tiles 128x128x16.
// 256 threads, each computes an 8x8 micro-tile with stride-16 row/col ownership
// (A smem reads broadcast, B smem reads consecutive -> conflict-free).
// Requires M%128==0, N%128==0, Kd%16==0. All shapes here satisfy that.
// ---------------------------------------------------------------------------
__global__ __launch_bounds__(256, 2) void sgemm_kernel(
    const float* __restrict__ A, const float* __restrict__ B,
    float* __restrict__ C, int M, int N, int Kd)
{
    __shared__ float As[16][132];   // transposed A tile: As[k][m]
    __shared__ float Bs[16][132];   // Bs[k][n]

    const int tid = threadIdx.x;
    const int tx = tid & 15;        // col group
    const int ty = tid >> 4;        // row group
    const int row0 = blockIdx.y * 128;
    const int col0 = blockIdx.x * 128;

    // A tile loader: 128 rows x 16 cols = 512 float4, 2 per thread
    const int a_row  = tid >> 2;          // 0..63
    const int a_col4 = (tid & 3) * 4;     // 0,4,8,12
    // B tile loader: 16 rows x 128 cols = 512 float4, 2 per thread
    const int b_row  = tid >> 5;          // 0..7
    const int b_col4 = (tid & 31) * 4;    // 0..124

    float acc[8][8];
#pragma unroll
    for (int i = 0; i < 8; i++)
#pragma unroll
        for (int j = 0; j < 8; j++) acc[i][j] = 0.0f;

    for (int k0 = 0; k0 < Kd; k0 += 16) {
        float4 av0 = *(const float4*)&A[(size_t)(row0 + a_row)       * Kd + k0 + a_col4];
        float4 av1 = *(const float4*)&A[(size_t)(row0 + a_row + 64)  * Kd + k0 + a_col4];
        float4 bv0 = *(const float4*)&B[(size_t)(k0 + b_row)         * N  + col0 + b_col4];
        float4 bv1 = *(const float4*)&B[(size_t)(k0 + b_row + 8)     * N  + col0 + b_col4];

        As[a_col4 + 0][a_row] = av0.x;
        As[a_col4 + 1][a_row] = av0.y;
        As[a_col4 + 2][a_row] = av0.z;
        As[a_col4 + 3][a_row] = av0.w;
        As[a_col4 + 0][a_row + 64] = av1.x;
        As[a_col4 + 1][a_row + 64] = av1.y;
        As[a_col4 + 2][a_row + 64] = av1.z;
        As[a_col4 + 3][a_row + 64] = av1.w;
        *(float4*)&Bs[b_row][b_col4]     = bv0;
        *(float4*)&Bs[b_row + 8][b_col4] = bv1;
        __syncthreads();

#pragma unroll
        for (int k = 0; k < 16; k++) {
            float a[8], b[8];
#pragma unroll
            for (int i = 0; i < 8; i++) a[i] = As[k][ty + 16 * i];
#pragma unroll
            for (int j = 0; j < 8; j++) b[j] = Bs[k][tx + 16 * j];
#pragma unroll
            for (int i = 0; i < 8; i++)
#pragma unroll
                for (int j = 0; j < 8; j++) acc[i][j] += a[i] * b[j];
        }
        __syncthreads();
    }

#pragma unroll
    for (int i = 0; i < 8; i++) {
        const int r = row0 + ty + 16 * i;
#pragma unroll
        for (int j = 0; j < 8; j++)
            C[(size_t)r * N + col0 + tx + 16 * j] = acc[i][j];
    }
}

// ---------------------------------------------------------------------------
// NeoX RoPE applied in-place to q heads (0..15) and k heads (16..19) of g_qkv.
// grid = (T, 20), 64 threads (one per rotation pair).
// ---------------------------------------------------------------------------
__global__ void rope_kernel(float* __restrict__ qkv, const int* __restrict__ pos)
{
    const int t = blockIdx.x;
    const int head = blockIdx.y;          // 0..19 (q: 0-15, k: 16-19)
    const int j = threadIdx.x;            // 0..63
    const float p = (float)pos[t];
    const float invf = powf(10000.0f, -((float)j) * (1.0f / 64.0f));
    float s, c;
    sincosf(p * invf, &s, &c);
    float* b = qkv + (size_t)t * QKV_N + head * HD;
    const float x1 = b[j];
    const float x2 = b[j + 64];
    b[j]      = x1 * c - x2 * s;
    b[j + 64] = x2 * c + x1 * s;
}

// ---------------------------------------------------------------------------
// Flash attention, fp32. BQ=BK=64, D=128. 256 threads.
// Thread (r = tid>>4, c = tid&15) owns score rows {r+16i}, score cols {c+16j},
// and output cols {c+16j} (stride-16 ownership => conflict-free smem access).
// ---------------------------------------------------------------------------
#define QP 132            // padded row pitch for Q/K/V tiles (floats)
#define PP 68             // padded row pitch for P tile
#define ATTN_SMEM ((3 * 64 * QP + 64 * PP) * 4)   // 118784 bytes

__global__ __launch_bounds__(256) void attn_kernel(
    const float* __restrict__ qkv, float* __restrict__ ctx)
{
    extern __shared__ float smf[];
    float* Qs = smf;                    // [64][QP]
    float* Ks = smf + 64 * QP;          // [64][QP]
    float* Vs = smf + 2 * 64 * QP;      // [64][QP]
    float* Ps = smf + 3 * 64 * QP;      // [64][PP]

    const int tid = threadIdx.x;
    const int c = tid & 15;
    const int r = tid >> 4;
    const int qb = (int)gridDim.x - 1 - (int)blockIdx.x;  // heavy blocks first
    const int h = blockIdx.y;
    const int kvh = h >> 2;             // GQA: 4 q heads per kv head
    const int q0 = qb * 64;
    const float scale = 0.088388347648318447f;  // 1/sqrt(128)

    // Load and pre-scale Q tile (64 x 128)
#pragma unroll
    for (int it = 0; it < 8; ++it) {
        const int idx = it * 256 + tid;
        const int row = idx >> 5;
        const int c4 = (idx & 31) << 2;
        float4 v = *(const float4*)&qkv[(size_t)(q0 + row) * QKV_N + h * HD + c4];
        v.x *= scale; v.y *= scale; v.z *= scale; v.w *= scale;
        *(float4*)&Qs[row * QP + c4] = v;
    }

    float acc[4][8];
    float m_run[4], l_run[4];
#pragma unroll
    for (int i = 0; i < 4; i++) {
        m_run[i] = -1e30f; l_run[i] = 0.0f;
#pragma unroll
        for (int j = 0; j < 8; j++) acc[i][j] = 0.0f;
    }

    for (int kb = 0; kb <= qb; ++kb) {
        const int k0 = kb * 64;
        __syncthreads();   // protect Ps/Vs from previous iteration (and Q on iter 0)

        // Load K and V tiles (64 x 128 each)
#pragma unroll
        for (int it = 0; it < 8; ++it) {
            const int idx = it * 256 + tid;
            const int row = idx >> 5;
            const int c4 = (idx & 31) << 2;
            const size_t base = (size_t)(k0 + row) * QKV_N + kvh * HD + c4;
            *(float4*)&Ks[row * QP + c4] = *(const float4*)&qkv[base + NH * HD];
            *(float4*)&Vs[row * QP + c4] = *(const float4*)&qkv[base + (NH + NKV) * HD];
        }
        __syncthreads();

        // S = Q @ K^T  (4x4 per thread)
        float s[4][4];
#pragma unroll
        for (int i = 0; i < 4; i++)
#pragma unroll
            for (int j = 0; j < 4; j++) s[i][j] = 0.0f;

#pragma unroll 8
        for (int d = 0; d < 128; d += 4) {
            float4 qv[4], kv[4];
#pragma unroll
            for (int i = 0; i < 4; i++) qv[i] = *(const float4*)&Qs[(r + 16 * i) * QP + d];
#pragma unroll
            for (int j = 0; j < 4; j++) kv[j] = *(const float4*)&Ks[(c + 16 * j) * QP + d];
#pragma unroll
            for (int i = 0; i < 4; i++)
#pragma unroll
                for (int j = 0; j < 4; j++)
                    s[i][j] += qv[i].x * kv[j].x + qv[i].y * kv[j].y +
                               qv[i].z * kv[j].z + qv[i].w * kv[j].w;
        }

        // Causal mask (only the diagonal block needs it)
        if (kb == qb) {
#pragma unroll
            for (int i = 0; i < 4; i++) {
                const int ri = r + 16 * i;
#pragma unroll
                for (int j = 0; j < 4; j++)
                    if (c + 16 * j > ri) s[i][j] = -1e30f;
            }
        }

        // Online softmax (row stats reduced across the 16 lanes sharing r)
#pragma unroll
        for (int i = 0; i < 4; i++) {
            float mloc = s[i][0];
#pragma unroll
            for (int j = 1; j < 4; j++) mloc = fmaxf(mloc, s[i][j]);
#pragma unroll
            for (int off = 8; off >= 1; off >>= 1)
                mloc = fmaxf(mloc, __shfl_xor_sync(0xffffffffu, mloc, off));
            const float mn = fmaxf(m_run[i], mloc);
            const float corr = __expf(m_run[i] - mn);
            m_run[i] = mn;
            float rs = 0.0f;
#pragma unroll
            for (int j = 0; j < 4; j++) {
                const float p = __expf(s[i][j] - mn);
                s[i][j] = p;
                rs += p;
            }
#pragma unroll
            for (int off = 8; off >= 1; off >>= 1)
                rs += __shfl_xor_sync(0xffffffffu, rs, off);
            l_run[i] = l_run[i] * corr + rs;
#pragma unroll
            for (int j = 0; j < 8; j++) acc[i][j] *= corr;
        }

        // Stage P to smem
#pragma unroll
        for (int i = 0; i < 4; i++)
#pragma unroll
            for (int j = 0; j < 4; j++)
                Ps[(r + 16 * i) * PP + c + 16 * j] = s[i][j];
        __syncthreads();

        // O += P @ V   (P reads broadcast, V reads consecutive)
#pragma unroll 4
        for (int k = 0; k < 64; k++) {
            float pr[4];
#pragma unroll
            for (int i = 0; i < 4; i++) pr[i] = Ps[(r + 16 * i) * PP + k];
#pragma unroll
            for (int j = 0; j < 8; j++) {
                const float v = Vs[k * QP + c + 16 * j];
#pragma unroll
                for (int i = 0; i < 4; i++) acc[i][j] += pr[i] * v;
            }
        }
    }

    // Epilogue: normalize and write ctx[t, h*128 + d]
#pragma unroll
    for (int i = 0; i < 4; i++) {
        const float inv = 1.0f / l_run[i];
        const int row = q0 + r + 16 * i;
#pragma unroll
        for (int j = 0; j < 8; j++)
            ctx[(size_t)row * CTX_N + h * HD + c + 16 * j] = acc[i][j] * inv;
    }
}

// ---------------------------------------------------------------------------
// Launch: qkv GEMM -> RoPE -> flash attention -> output GEMM
// Inputs (metadata order): hidden_states f32, position_ids i32, Wqkv f32, Wo f32
// ---------------------------------------------------------------------------
extern "C" void kernel_launch(void* const* d_in, const int* in_sizes, int n_in,
                              void* d_out, int out_size)
{
    const float* hidden = (const float*)d_in[0];
    const int*   pos    = (const int*)d_in[1];
    const float* Wqkv   = (const float*)d_in[2];
    const float* Wo     = (const float*)d_in[3];
    float* out = (float*)d_out;

    float *qkv_d = nullptr, *ctx_d = nullptr;
    cudaGetSymbolAddress((void**)&qkv_d, g_qkv);
    cudaGetSymbolAddress((void**)&ctx_d, g_ctx);

    cudaFuncSetAttribute(attn_kernel, cudaFuncAttributeMaxDynamicSharedMemorySize,
                         ATTN_SMEM);

    // 1) qkv = hidden @ Wqkv : [2048,2048] x [2048,3072]
    dim3 g1(QKV_N / 128, T_SEQ / 128);
    sgemm_kernel<<<g1, 256>>>(hidden, Wqkv, qkv_d, T_SEQ, QKV_N, HID_DIM);

    // 2) RoPE on q and k heads
    rope_kernel<<<dim3(T_SEQ, NH + NKV), 64>>>(qkv_d, pos);

    // 3) causal GQA flash attention
    attn_kernel<<<dim3(T_SEQ / 64, NH), 256, ATTN_SMEM>>>(qkv_d, ctx_d);

    // 4) out = ctx @ Wo : [2048,2048] x [2048,2048]
    dim3 g3(HID_DIM / 128, T_SEQ / 128);
    sgemm_kernel<<<g3, 256>>>(ctx_d, Wo, out, T_SEQ, HID_DIM, CTX_N);
}

// round 3
// speedup vs baseline: 1.4389x; 1.4389x over previous
#include <cuda_runtime.h>
#include <cuda_bf16.h>
#include <math.h>
#include <cstdint>
#include <cstddef>

#define T_SEQ 2048
#define HID_DIM 2048
#define NH 16
#define NKV 4
#define HD 128
#define QKV_N ((NH + 2 * NKV) * HD)   // 3072
#define CTX_N (NH * HD)               // 2048

// ---------------- scratch (no cudaMalloc allowed) ----------------
__device__ float g_qkv[T_SEQ * QKV_N];            // 25 MB
__device__ float g_ctx[T_SEQ * CTX_N];            // 16 MB
__device__ __nv_bfloat16 g_hid_hi[T_SEQ * HID_DIM];
__device__ __nv_bfloat16 g_hid_lo[T_SEQ * HID_DIM];
__device__ __nv_bfloat16 g_ctx_hi[T_SEQ * CTX_N];
__device__ __nv_bfloat16 g_ctx_lo[T_SEQ * CTX_N];
__device__ __nv_bfloat16 g_wqkvT_hi[QKV_N * HID_DIM];   // [N][K]
__device__ __nv_bfloat16 g_wqkvT_lo[QKV_N * HID_DIM];
__device__ __nv_bfloat16 g_woT_hi[HID_DIM * CTX_N];     // [N][K]
__device__ __nv_bfloat16 g_woT_lo[HID_DIM * CTX_N];

// ---------------------------------------------------------------------------
// Split fp32 -> (hi, lo) bf16, elementwise (for A operands, kept row-major).
// ---------------------------------------------------------------------------
__global__ void split_rows_kernel(const float* __restrict__ X,
                                  __nv_bfloat16* __restrict__ hi,
                                  __nv_bfloat16* __restrict__ lo)
{
    const size_t i = ((size_t)blockIdx.x * blockDim.x + threadIdx.x) * 4;
    float4 v = *(const float4*)&X[i];
    __nv_bfloat16 h0 = __float2bfloat16(v.x);
    __nv_bfloat16 h1 = __float2bfloat16(v.y);
    __nv_bfloat16 h2 = __float2bfloat16(v.z);
    __nv_bfloat16 h3 = __float2bfloat16(v.w);
    __nv_bfloat162 hh0; hh0.x = h0; hh0.y = h1;
    __nv_bfloat162 hh1; hh1.x = h2; hh1.y = h3;
    *(__nv_bfloat162*)&hi[i]     = hh0;
    *(__nv_bfloat162*)&hi[i + 2] = hh1;
    __nv_bfloat162 ll0, ll1;
    ll0.x = __float2bfloat16(v.x - __bfloat162float(h0));
    ll0.y = __float2bfloat16(v.y - __bfloat162float(h1));
    ll1.x = __float2bfloat16(v.z - __bfloat162float(h2));
    ll1.y = __float2bfloat16(v.w - __bfloat162float(h3));
    *(__nv_bfloat162*)&lo[i]     = ll0;
    *(__nv_bfloat162*)&lo[i + 2] = ll1;
}

// ---------------------------------------------------------------------------
// Split + transpose: W[Kd][N] fp32 -> Wt_hi/lo[N][Kd] bf16 (K-major for mma B).
// block (32,8), 32x32 tile.
// ---------------------------------------------------------------------------
__global__ void split_T_kernel(const float* __restrict__ W,
                               __nv_bfloat16* __restrict__ hi,
                               __nv_bfloat16* __restrict__ lo,
                               int Kd, int N)
{
    __shared__ float tile[32][33];
    const int n0 = blockIdx.x * 32;
    const int k0 = blockIdx.y * 32;
    const int tx = threadIdx.x, ty = threadIdx.y;
#pragma unroll
    for (int i = 0; i < 32; i += 8)
        tile[ty + i][tx] = W[(size_t)(k0 + ty + i) * N + n0 + tx];
    __syncthreads();
#pragma unroll
    for (int i = 0; i < 32; i += 8) {
        const float v = tile[tx][ty + i];
        const __nv_bfloat16 h = __float2bfloat16(v);
        const size_t o = (size_t)(n0 + ty + i) * Kd + k0 + tx;
        hi[o] = h;
        lo[o] = __float2bfloat16(v - __bfloat162float(h));
    }
}

// ---------------------------------------------------------------------------
// bf16x3 GEMM on tensor cores: C = Ah*Bh + Ah*Bl + Al*Bh  (fp32 accumulate).
// A: [M][K] row-major bf16 (hi/lo). B: [N][K] K-major bf16 (hi/lo).
// Block tile 128x128, KC=32, 8 warps (2x4), warp tile 64x32, mma m16n8k16.
// ---------------------------------------------------------------------------
#define MMA_BF16(d, a, b)                                                    \
    asm volatile(                                                            \
        "mma.sync.aligned.m16n8k16.row.col.f32.bf16.bf16.f32 "               \
        "{%0,%1,%2,%3}, {%4,%5,%6,%7}, {%8,%9}, {%0,%1,%2,%3};\n"            \
        : "+f"((d)[0]), "+f"((d)[1]), "+f"((d)[2]), "+f"((d)[3])             \
        : "r"((a)[0]), "r"((a)[1]), "r"((a)[2]), "r"((a)[3]),                \
          "r"((b)[0]), "r"((b)[1]))

#define SPITCH 40   // smem row pitch in bf16 elems (conflict-free for frag LDS)

__global__ __launch_bounds__(256, 1) void gemm_bf16x3_kernel(
    const __nv_bfloat16* __restrict__ Ah, const __nv_bfloat16* __restrict__ Al,
    const __nv_bfloat16* __restrict__ Bh, const __nv_bfloat16* __restrict__ Bl,
    float* __restrict__ C, int M, int N, int Kd)
{
    __shared__ __nv_bfloat16 sAh[128 * SPITCH];
    __shared__ __nv_bfloat16 sAl[128 * SPITCH];
    __shared__ __nv_bfloat16 sBh[128 * SPITCH];
    __shared__ __nv_bfloat16 sBl[128 * SPITCH];

    const int tid  = threadIdx.x;
    const int lane = tid & 31;
    const int wid  = tid >> 5;
    const int g    = lane >> 2;       // 0..7
    const int cq   = lane & 3;        // 0..3
    const int wm   = wid & 1;         // warp row (2)
    const int wn   = wid >> 1;        // warp col (4)
    const int row0 = blockIdx.y * 128;
    const int col0 = blockIdx.x * 128;

    // tile loader mapping: 128 rows x 32 cols per array, 2 x uint4 per thread
    const int lr = tid >> 1;
    const int lc = (tid & 1) * 16;
    const __nv_bfloat16* pAh = Ah + (size_t)(row0 + lr) * Kd + lc;
    const __nv_bfloat16* pAl = Al + (size_t)(row0 + lr) * Kd + lc;
    const __nv_bfloat16* pBh = Bh + (size_t)(col0 + lr) * Kd + lc;
    const __nv_bfloat16* pBl = Bl + (size_t)(col0 + lr) * Kd + lc;
    const int sidx = lr * SPITCH + lc;

    float acc[4][4][4];
#pragma unroll
    for (int i = 0; i < 4; i++)
#pragma unroll
        for (int j = 0; j < 4; j++)
#pragma unroll
            for (int e = 0; e < 4; e++) acc[i][j][e] = 0.0f;

    // prefetch stage 0
    uint4 rah0 = *(const uint4*)(pAh),     rah1 = *(const uint4*)(pAh + 8);
    uint4 ral0 = *(const uint4*)(pAl),     ral1 = *(const uint4*)(pAl + 8);
    uint4 rbh0 = *(const uint4*)(pBh),     rbh1 = *(const uint4*)(pBh + 8);
    uint4 rbl0 = *(const uint4*)(pBl),     rbl1 = *(const uint4*)(pBl + 8);

    for (int k0 = 0; k0 < Kd; k0 += 32) {
        *(uint4*)&sAh[sidx] = rah0;  *(uint4*)&sAh[sidx + 8] = rah1;
        *(uint4*)&sAl[sidx] = ral0;  *(uint4*)&sAl[sidx + 8] = ral1;
        *(uint4*)&sBh[sidx] = rbh0;  *(uint4*)&sBh[sidx + 8] = rbh1;
        *(uint4*)&sBl[sidx] = rbl0;  *(uint4*)&sBl[sidx + 8] = rbl1;
        __syncthreads();

        if (k0 + 32 < Kd) {
            const int kn = k0 + 32;
            rah0 = *(const uint4*)(pAh + kn); rah1 = *(const uint4*)(pAh + kn + 8);
            ral0 = *(const uint4*)(pAl + kn); ral1 = *(const uint4*)(pAl + kn + 8);
            rbh0 = *(const uint4*)(pBh + kn); rbh1 = *(const uint4*)(pBh + kn + 8);
            rbl0 = *(const uint4*)(pBl + kn); rbl1 = *(const uint4*)(pBl + kn + 8);
        }

#pragma unroll
        for (int ks = 0; ks < 32; ks += 16) {
            uint32_t ah[4][4], al[4][4], bh[4][2], bl[4][2];
#pragma unroll
            for (int mt = 0; mt < 4; mt++) {
                const int rb = (wm * 64 + mt * 16 + g) * SPITCH + ks + 2 * cq;
                ah[mt][0] = *(const uint32_t*)&sAh[rb];
                ah[mt][1] = *(const uint32_t*)&sAh[rb + 8 * SPITCH];
                ah[mt][2] = *(const uint32_t*)&sAh[rb + 8];
                ah[mt][3] = *(const uint32_t*)&sAh[rb + 8 * SPITCH + 8];
                al[mt][0] = *(const uint32_t*)&sAl[rb];
                al[mt][1] = *(const uint32_t*)&sAl[rb + 8 * SPITCH];
                al[mt][2] = *(const uint32_t*)&sAl[rb + 8];
                al[mt][3] = *(const uint32_t*)&sAl[rb + 8 * SPITCH + 8];
            }
#pragma unroll
            for (int nt = 0; nt < 4; nt++) {
                const int nb = (wn * 32 + nt * 8 + g) * SPITCH + ks + 2 * cq;
                bh[nt][0] = *(const uint32_t*)&sBh[nb];
                bh[nt][1] = *(const uint32_t*)&sBh[nb + 8];
                bl[nt][0] = *(const uint32_t*)&sBl[nb];
                bl[nt][1] = *(const uint32_t*)&sBl[nb + 8];
            }
#pragma unroll
            for (int mt = 0; mt < 4; mt++)
#pragma unroll
                for (int nt = 0; nt < 4; nt++) MMA_BF16(acc[mt][nt], ah[mt], bh[nt]);
#pragma unroll
            for (int mt = 0; mt < 4; mt++)
#pragma unroll
                for (int nt = 0; nt < 4; nt++) MMA_BF16(acc[mt][nt], ah[mt], bl[nt]);
#pragma unroll
            for (int mt = 0; mt < 4; mt++)
#pragma unroll
                for (int nt = 0; nt < 4; nt++) MMA_BF16(acc[mt][nt], al[mt], bh[nt]);
        }
        __syncthreads();
    }

#pragma unroll
    for (int mt = 0; mt < 4; mt++) {
        const int r0 = row0 + wm * 64 + mt * 16 + g;
#pragma unroll
        for (int nt = 0; nt < 4; nt++) {
            const int cb = col0 + wn * 32 + nt * 8 + 2 * cq;
            *(float2*)&C[(size_t)r0 * N + cb]       = make_float2(acc[mt][nt][0], acc[mt][nt][1]);
            *(float2*)&C[(size_t)(r0 + 8) * N + cb] = make_float2(acc[mt][nt][2], acc[mt][nt][3]);
        }
    }
}

// ---------------------------------------------------------------------------
// NeoX RoPE in-place on q heads (0..15) and k heads (16..19) of g_qkv.
// ---------------------------------------------------------------------------
__global__ void rope_kernel(float* __restrict__ qkv, const int* __restrict__ pos)
{
    const int t = blockIdx.x;
    const int head = blockIdx.y;
    const int j = threadIdx.x;            // 0..63
    const float p = (float)pos[t];
    const float invf = powf(10000.0f, -((float)j) * (1.0f / 64.0f));
    float s, c;
    sincosf(p * invf, &s, &c);
    float* b = qkv + (size_t)t * QKV_N + head * HD;
    const float x1 = b[j];
    const float x2 = b[j + 64];
    b[j]      = x1 * c - x2 * s;
    b[j + 64] = x2 * c + x1 * s;
}

// ---------------------------------------------------------------------------
// Flash attention, fp32 (unchanged). BQ=BK=64, 256 threads.
// ---------------------------------------------------------------------------
#define QP 132
#define PP 68
#define ATTN_SMEM ((3 * 64 * QP + 64 * PP) * 4)

__global__ __launch_bounds__(256) void attn_kernel(
    const float* __restrict__ qkv, float* __restrict__ ctx)
{
    extern __shared__ float smf[];
    float* Qs = smf;
    float* Ks = smf + 64 * QP;
    float* Vs = smf + 2 * 64 * QP;
    float* Ps = smf + 3 * 64 * QP;

    const int tid = threadIdx.x;
    const int c = tid & 15;
    const int r = tid >> 4;
    const int qb = (int)gridDim.x - 1 - (int)blockIdx.x;
    const int h = blockIdx.y;
    const int kvh = h >> 2;
    const int q0 = qb * 64;
    const float scale = 0.088388347648318447f;

#pragma unroll
    for (int it = 0; it < 8; ++it) {
        const int idx = it * 256 + tid;
        const int row = idx >> 5;
        const int c4 = (idx & 31) << 2;
        float4 v = *(const float4*)&qkv[(size_t)(q0 + row) * QKV_N + h * HD + c4];
        v.x *= scale; v.y *= scale; v.z *= scale; v.w *= scale;
        *(float4*)&Qs[row * QP + c4] = v;
    }

    float acc[4][8];
    float m_run[4], l_run[4];
#pragma unroll
    for (int i = 0; i < 4; i++) {
        m_run[i] = -1e30f; l_run[i] = 0.0f;
#pragma unroll
        for (int j = 0; j < 8; j++) acc[i][j] = 0.0f;
    }

    for (int kb = 0; kb <= qb; ++kb) {
        const int k0 = kb * 64;
        __syncthreads();

#pragma unroll
        for (int it = 0; it < 8; ++it) {
            const int idx = it * 256 + tid;
            const int row = idx >> 5;
            const int c4 = (idx & 31) << 2;
            const size_t base = (size_t)(k0 + row) * QKV_N + kvh * HD + c4;
            *(float4*)&Ks[row * QP + c4] = *(const float4*)&qkv[base + NH * HD];
            *(float4*)&Vs[row * QP + c4] = *(const float4*)&qkv[base + (NH + NKV) * HD];
        }
        __syncthreads();

        float s[4][4];
#pragma unroll
        for (int i = 0; i < 4; i++)
#pragma unroll
            for (int j = 0; j < 4; j++) s[i][j] = 0.0f;

#pragma unroll 8
        for (int d = 0; d < 128; d += 4) {
            float4 qv[4], kv[4];
#pragma unroll
            for (int i = 0; i < 4; i++) qv[i] = *(const float4*)&Qs[(r + 16 * i) * QP + d];
#pragma unroll
            for (int j = 0; j < 4; j++) kv[j] = *(const float4*)&Ks[(c + 16 * j) * QP + d];
#pragma unroll
            for (int i = 0; i < 4; i++)
#pragma unroll
                for (int j = 0; j < 4; j++)
                    s[i][j] += qv[i].x * kv[j].x + qv[i].y * kv[j].y +
                               qv[i].z * kv[j].z + qv[i].w * kv[j].w;
        }

        if (kb == qb) {
#pragma unroll
            for (int i = 0; i < 4; i++) {
                const int ri = r + 16 * i;
#pragma unroll
                for (int j = 0; j < 4; j++)
                    if (c + 16 * j > ri) s[i][j] = -1e30f;
            }
        }

#pragma unroll
        for (int i = 0; i < 4; i++) {
            float mloc = s[i][0];
#pragma unroll
            for (int j = 1; j < 4; j++) mloc = fmaxf(mloc, s[i][j]);
#pragma unroll
            for (int off = 8; off >= 1; off >>= 1)
                mloc = fmaxf(mloc, __shfl_xor_sync(0xffffffffu, mloc, off));
            const float mn = fmaxf(m_run[i], mloc);
            const float corr = __expf(m_run[i] - mn);
            m_run[i] = mn;
            float rs = 0.0f;
#pragma unroll
            for (int j = 0; j < 4; j++) {
                const float p = __expf(s[i][j] - mn);
                s[i][j] = p;
                rs += p;
            }
#pragma unroll
            for (int off = 8; off >= 1; off >>= 1)
                rs += __shfl_xor_sync(0xffffffffu, rs, off);
            l_run[i] = l_run[i] * corr + rs;
#pragma unroll
            for (int j = 0; j < 8; j++) acc[i][j] *= corr;
        }

#pragma unroll
        for (int i = 0; i < 4; i++)
#pragma unroll
            for (int j = 0; j < 4; j++)
                Ps[(r + 16 * i) * PP + c + 16 * j] = s[i][j];
        __syncthreads();

#pragma unroll 4
        for (int k = 0; k < 64; k++) {
            float pr[4];
#pragma unroll
            for (int i = 0; i < 4; i++) pr[i] = Ps[(r + 16 * i) * PP + k];
#pragma unroll
            for (int j = 0; j < 8; j++) {
                const float v = Vs[k * QP + c + 16 * j];
#pragma unroll
                for (int i = 0; i < 4; i++) acc[i][j] += pr[i] * v;
            }
        }
    }

#pragma unroll
    for (int i = 0; i < 4; i++) {
        const float inv = 1.0f / l_run[i];
        const int row = q0 + r + 16 * i;
#pragma unroll
        for (int j = 0; j < 8; j++)
            ctx[(size_t)row * CTX_N + h * HD + c + 16 * j] = acc[i][j] * inv;
    }
}

// ---------------------------------------------------------------------------
// Launch pipeline.
// ---------------------------------------------------------------------------
extern "C" void kernel_launch(void* const* d_in, const int* in_sizes, int n_in,
                              void* d_out, int out_size)
{
    const float* hidden = (const float*)d_in[0];
    const int*   pos    = (const int*)d_in[1];
    const float* Wqkv   = (const float*)d_in[2];
    const float* Wo     = (const float*)d_in[3];
    float* out = (float*)d_out;

    float *qkv_d, *ctx_d;
    __nv_bfloat16 *hid_hi, *hid_lo, *ctx_hi, *ctx_lo;
    __nv_bfloat16 *wqkvT_hi, *wqkvT_lo, *woT_hi, *woT_lo;
    cudaGetSymbolAddress((void**)&qkv_d, g_qkv);
    cudaGetSymbolAddress((void**)&ctx_d, g_ctx);
    cudaGetSymbolAddress((void**)&hid_hi, g_hid_hi);
    cudaGetSymbolAddress((void**)&hid_lo, g_hid_lo);
    cudaGetSymbolAddress((void**)&ctx_hi, g_ctx_hi);
    cudaGetSymbolAddress((void**)&ctx_lo, g_ctx_lo);
    cudaGetSymbolAddress((void**)&wqkvT_hi, g_wqkvT_hi);
    cudaGetSymbolAddress((void**)&wqkvT_lo, g_wqkvT_lo);
    cudaGetSymbolAddress((void**)&woT_hi, g_woT_hi);
    cudaGetSymbolAddress((void**)&woT_lo, g_woT_lo);

    cudaFuncSetAttribute(attn_kernel, cudaFuncAttributeMaxDynamicSharedMemorySize,
                         ATTN_SMEM);

    // splits
    split_rows_kernel<<<(T_SEQ * HID_DIM) / (256 * 4), 256>>>(hidden, hid_hi, hid_lo);
    split_T_kernel<<<dim3(QKV_N / 32, HID_DIM / 32), dim3(32, 8)>>>(Wqkv, wqkvT_hi, wqkvT_lo, HID_DIM, QKV_N);
    split_T_kernel<<<dim3(HID_DIM / 32, CTX_N / 32), dim3(32, 8)>>>(Wo, woT_hi, woT_lo, CTX_N, HID_DIM);

    // 1) qkv = hidden @ Wqkv  (bf16x3 tensor-core GEMM)
    gemm_bf16x3_kernel<<<dim3(QKV_N / 128, T_SEQ / 128), 256>>>(
        hid_hi, hid_lo, wqkvT_hi, wqkvT_lo, qkv_d, T_SEQ, QKV_N, HID_DIM);

    // 2) RoPE
    rope_kernel<<<dim3(T_SEQ, NH + NKV), 64>>>(qkv_d, pos);

    // 3) causal GQA flash attention (fp32)
    attn_kernel<<<dim3(T_SEQ / 64, NH), 256, ATTN_SMEM>>>(qkv_d, ctx_d);

    // 4) out = ctx @ Wo  (bf16x3 tensor-core GEMM)
    split_rows_kernel<<<(T_SEQ * CTX_N) / (256 * 4), 256>>>(ctx_d, ctx_hi, ctx_lo);
    gemm_bf16x3_kernel<<<dim3(HID_DIM / 128, T_SEQ / 128), 256>>>(
        ctx_hi, ctx_lo, woT_hi, woT_lo, out, T_SEQ, HID_DIM, CTX_N);
}

// round 4
// speedup vs baseline: 2.3150x; 1.6089x over previous
#include <cuda_runtime.h>
#include <cuda_bf16.h>
#include <math.h>
#include <cstdint>
#include <cstddef>

#define T_SEQ 2048
#define HID_DIM 2048
#define NH 16
#define NKV 4
#define HD 128
#define QKV_N ((NH + 2 * NKV) * HD)   // 3072
#define CTX_N (NH * HD)               // 2048
#define SCALE 0.088388347648318447f   // 1/sqrt(128)

// ---------------- scratch (no cudaMalloc allowed) ----------------
__device__ float g_qkv[T_SEQ * QKV_N];            // 25 MB
__device__ __nv_bfloat16 g_hid_hi[T_SEQ * HID_DIM];
__device__ __nv_bfloat16 g_hid_lo[T_SEQ * HID_DIM];
__device__ __nv_bfloat16 g_wqkvT_hi[QKV_N * HID_DIM];   // [N][K]
__device__ __nv_bfloat16 g_wqkvT_lo[QKV_N * HID_DIM];
__device__ __nv_bfloat16 g_woT_hi[HID_DIM * CTX_N];     // [N][K]
__device__ __nv_bfloat16 g_woT_lo[HID_DIM * CTX_N];
// attention operands (bf16 hi/lo, rope+scale applied)
__device__ __nv_bfloat16 g_qh[T_SEQ * NH * HD];
__device__ __nv_bfloat16 g_ql[T_SEQ * NH * HD];
__device__ __nv_bfloat16 g_kh[T_SEQ * NKV * HD];
__device__ __nv_bfloat16 g_kl[T_SEQ * NKV * HD];
__device__ __nv_bfloat16 g_vh[T_SEQ * NKV * HD];
__device__ __nv_bfloat16 g_vl[T_SEQ * NKV * HD];
// attention output, pre-split for GEMM2
__device__ __nv_bfloat16 g_ctx_hi[T_SEQ * CTX_N];
__device__ __nv_bfloat16 g_ctx_lo[T_SEQ * CTX_N];

// ---------------- tiny helpers ----------------
__device__ __forceinline__ uint32_t packbf(float lo, float hi) {
    uint32_t r;
    asm("cvt.rn.bf16x2.f32 %0, %1, %2;" : "=r"(r) : "f"(hi), "f"(lo));
    return r;
}
__device__ __forceinline__ float bfres(float x) {   // x - bf16(x)
    return x - __bfloat162float(__float2bfloat16(x));
}

#define MMA4(d, a, b0_, b1_)                                                  \
    asm volatile(                                                             \
        "mma.sync.aligned.m16n8k16.row.col.f32.bf16.bf16.f32 "                \
        "{%0,%1,%2,%3}, {%4,%5,%6,%7}, {%8,%9}, {%0,%1,%2,%3};\n"             \
        : "+f"((d)[0]), "+f"((d)[1]), "+f"((d)[2]), "+f"((d)[3])              \
        : "r"((a)[0]), "r"((a)[1]), "r"((a)[2]), "r"((a)[3]),                 \
          "r"(b0_), "r"(b1_))

#define LDSM_X4(r0, r1, r2, r3, a)                                            \
    asm volatile("ldmatrix.sync.aligned.m8n8.x4.shared.b16 {%0,%1,%2,%3}, [%4];" \
                 : "=r"(r0), "=r"(r1), "=r"(r2), "=r"(r3) : "r"(a))

#define LDSM_X4_T(r0, r1, r2, r3, a)                                          \
    asm volatile("ldmatrix.sync.aligned.m8n8.x4.trans.shared.b16 {%0,%1,%2,%3}, [%4];" \
                 : "=r"(r0), "=r"(r1), "=r"(r2), "=r"(r3) : "r"(a))

// ---------------------------------------------------------------------------
// Split fp32 -> (hi, lo) bf16, elementwise (A operands, row-major).
// ---------------------------------------------------------------------------
__global__ void split_rows_kernel(const float* __restrict__ X,
                                  __nv_bfloat16* __restrict__ hi,
                                  __nv_bfloat16* __restrict__ lo)
{
    const size_t i = ((size_t)blockIdx.x * blockDim.x + threadIdx.x) * 4;
    float4 v = *(const float4*)&X[i];
    __nv_bfloat16 h0 = __float2bfloat16(v.x);
    __nv_bfloat16 h1 = __float2bfloat16(v.y);
    __nv_bfloat16 h2 = __float2bfloat16(v.z);
    __nv_bfloat16 h3 = __float2bfloat16(v.w);
    __nv_bfloat162 hh0; hh0.x = h0; hh0.y = h1;
    __nv_bfloat162 hh1; hh1.x = h2; hh1.y = h3;
    *(__nv_bfloat162*)&hi[i]     = hh0;
    *(__nv_bfloat162*)&hi[i + 2] = hh1;
    __nv_bfloat162 ll0, ll1;
    ll0.x = __float2bfloat16(v.x - __bfloat162float(h0));
    ll0.y = __float2bfloat16(v.y - __bfloat162float(h1));
    ll1.x = __float2bfloat16(v.z - __bfloat162float(h2));
    ll1.y = __float2bfloat16(v.w - __bfloat162float(h3));
    *(__nv_bfloat162*)&lo[i]     = ll0;
    *(__nv_bfloat162*)&lo[i + 2] = ll1;
}

// ---------------------------------------------------------------------------
// Split + transpose: W[Kd][N] fp32 -> Wt_hi/lo[N][Kd] bf16.
// ---------------------------------------------------------------------------
__global__ void split_T_kernel(const float* __restrict__ W,
                               __nv_bfloat16* __restrict__ hi,
                               __nv_bfloat16* __restrict__ lo,
                               int Kd, int N)
{
    __shared__ float tile[32][33];
    const int n0 = blockIdx.x * 32;
    const int k0 = blockIdx.y * 32;
    const int tx = threadIdx.x, ty = threadIdx.y;
#pragma unroll
    for (int i = 0; i < 32; i += 8)
        tile[ty + i][tx] = W[(size_t)(k0 + ty + i) * N + n0 + tx];
    __syncthreads();
#pragma unroll
    for (int i = 0; i < 32; i += 8) {
        const float v = tile[tx][ty + i];
        const __nv_bfloat16 h = __float2bfloat16(v);
        const size_t o = (size_t)(n0 + ty + i) * Kd + k0 + tx;
        hi[o] = h;
        lo[o] = __float2bfloat16(v - __bfloat162float(h));
    }
}

// ---------------------------------------------------------------------------
// bf16x3 GEMM on tensor cores (unchanged from round 3).
// ---------------------------------------------------------------------------
#define SPITCH 40

__global__ __launch_bounds__(256, 1) void gemm_bf16x3_kernel(
    const __nv_bfloat16* __restrict__ Ah, const __nv_bfloat16* __restrict__ Al,
    const __nv_bfloat16* __restrict__ Bh, const __nv_bfloat16* __restrict__ Bl,
    float* __restrict__ C, int M, int N, int Kd)
{
    __shared__ __nv_bfloat16 sAh[128 * SPITCH];
    __shared__ __nv_bfloat16 sAl[128 * SPITCH];
    __shared__ __nv_bfloat16 sBh[128 * SPITCH];
    __shared__ __nv_bfloat16 sBl[128 * SPITCH];

    const int tid  = threadIdx.x;
    const int lane = tid & 31;
    const int wid  = tid >> 5;
    const int g    = lane >> 2;
    const int cq   = lane & 3;
    const int wm   = wid & 1;
    const int wn   = wid >> 1;
    const int row0 = blockIdx.y * 128;
    const int col0 = blockIdx.x * 128;

    const int lr = tid >> 1;
    const int lc = (tid & 1) * 16;
    const __nv_bfloat16* pAh = Ah + (size_t)(row0 + lr) * Kd + lc;
    const __nv_bfloat16* pAl = Al + (size_t)(row0 + lr) * Kd + lc;
    const __nv_bfloat16* pBh = Bh + (size_t)(col0 + lr) * Kd + lc;
    const __nv_bfloat16* pBl = Bl + (size_t)(col0 + lr) * Kd + lc;
    const int sidx = lr * SPITCH + lc;

    float acc[4][4][4];
#pragma unroll
    for (int i = 0; i < 4; i++)
#pragma unroll
        for (int j = 0; j < 4; j++)
#pragma unroll
            for (int e = 0; e < 4; e++) acc[i][j][e] = 0.0f;

    uint4 rah0 = *(const uint4*)(pAh),     rah1 = *(const uint4*)(pAh + 8);
    uint4 ral0 = *(const uint4*)(pAl),     ral1 = *(const uint4*)(pAl + 8);
    uint4 rbh0 = *(const uint4*)(pBh),     rbh1 = *(const uint4*)(pBh + 8);
    uint4 rbl0 = *(const uint4*)(pBl),     rbl1 = *(const uint4*)(pBl + 8);

    for (int k0 = 0; k0 < Kd; k0 += 32) {
        *(uint4*)&sAh[sidx] = rah0;  *(uint4*)&sAh[sidx + 8] = rah1;
        *(uint4*)&sAl[sidx] = ral0;  *(uint4*)&sAl[sidx + 8] = ral1;
        *(uint4*)&sBh[sidx] = rbh0;  *(uint4*)&sBh[sidx + 8] = rbh1;
        *(uint4*)&sBl[sidx] = rbl0;  *(uint4*)&sBl[sidx + 8] = rbl1;
        __syncthreads();

        if (k0 + 32 < Kd) {
            const int kn = k0 + 32;
            rah0 = *(const uint4*)(pAh + kn); rah1 = *(const uint4*)(pAh + kn + 8);
            ral0 = *(const uint4*)(pAl + kn); ral1 = *(const uint4*)(pAl + kn + 8);
            rbh0 = *(const uint4*)(pBh + kn); rbh1 = *(const uint4*)(pBh + kn + 8);
            rbl0 = *(const uint4*)(pBl + kn); rbl1 = *(const uint4*)(pBl + kn + 8);
        }

#pragma unroll
        for (int ks = 0; ks < 32; ks += 16) {
            uint32_t ah[4][4], al[4][4], bh[4][2], bl[4][2];
#pragma unroll
            for (int mt = 0; mt < 4; mt++) {
                const int rb = (wm * 64 + mt * 16 + g) * SPITCH + ks + 2 * cq;
                ah[mt][0] = *(const uint32_t*)&sAh[rb];
                ah[mt][1] = *(const uint32_t*)&sAh[rb + 8 * SPITCH];
                ah[mt][2] = *(const uint32_t*)&sAh[rb + 8];
                ah[mt][3] = *(const uint32_t*)&sAh[rb + 8 * SPITCH + 8];
                al[mt][0] = *(const uint32_t*)&sAl[rb];
                al[mt][1] = *(const uint32_t*)&sAl[rb + 8 * SPITCH];
                al[mt][2] = *(const uint32_t*)&sAl[rb + 8];
                al[mt][3] = *(const uint32_t*)&sAl[rb + 8 * SPITCH + 8];
            }
#pragma unroll
            for (int nt = 0; nt < 4; nt++) {
                const int nb = (wn * 32 + nt * 8 + g) * SPITCH + ks + 2 * cq;
                bh[nt][0] = *(const uint32_t*)&sBh[nb];
                bh[nt][1] = *(const uint32_t*)&sBh[nb + 8];
                bl[nt][0] = *(const uint32_t*)&sBl[nb];
                bl[nt][1] = *(const uint32_t*)&sBl[nb + 8];
            }
#pragma unroll
            for (int mt = 0; mt < 4; mt++)
#pragma unroll
                for (int nt = 0; nt < 4; nt++) MMA4(acc[mt][nt], ah[mt], bh[nt][0], bh[nt][1]);
#pragma unroll
            for (int mt = 0; mt < 4; mt++)
#pragma unroll
                for (int nt = 0; nt < 4; nt++) MMA4(acc[mt][nt], ah[mt], bl[nt][0], bl[nt][1]);
#pragma unroll
            for (int mt = 0; mt < 4; mt++)
#pragma unroll
                for (int nt = 0; nt < 4; nt++) MMA4(acc[mt][nt], al[mt], bh[nt][0], bh[nt][1]);
        }
        __syncthreads();
    }

#pragma unroll
    for (int mt = 0; mt < 4; mt++) {
        const int r0 = row0 + wm * 64 + mt * 16 + g;
#pragma unroll
        for (int nt = 0; nt < 4; nt++) {
            const int cb = col0 + wn * 32 + nt * 8 + 2 * cq;
            *(float2*)&C[(size_t)r0 * N + cb]       = make_float2(acc[mt][nt][0], acc[mt][nt][1]);
            *(float2*)&C[(size_t)(r0 + 8) * N + cb] = make_float2(acc[mt][nt][2], acc[mt][nt][3]);
        }
    }
}

// ---------------------------------------------------------------------------
// RoPE + scale + hi/lo bf16 split. One block per token t, 128 threads.
// q -> g_qh/ql [t][16][128] (pre-scaled), k -> g_kh/kl [t][4][128], v -> g_vh/vl.
// ---------------------------------------------------------------------------
__global__ void rope_split_kernel(const float* __restrict__ qkv,
                                  const int* __restrict__ pos,
                                  __nv_bfloat16* __restrict__ qh, __nv_bfloat16* __restrict__ ql,
                                  __nv_bfloat16* __restrict__ kh, __nv_bfloat16* __restrict__ kl,
                                  __nv_bfloat16* __restrict__ vh, __nv_bfloat16* __restrict__ vl)
{
    const int t = blockIdx.x;
    const int tid = threadIdx.x;
    const float p = (float)pos[t];
    const float* base = qkv + (size_t)t * QKV_N;

    // q heads: 16 * 64 pairs
#pragma unroll
    for (int it = 0; it < 8; it++) {
        const int item = it * 128 + tid;
        const int head = item >> 6, j = item & 63;
        const float invf = powf(10000.0f, -((float)j) * (1.0f / 64.0f));
        float s, c; sincosf(p * invf, &s, &c);
        const float x1 = base[head * HD + j];
        const float x2 = base[head * HD + j + 64];
        const float y1 = (x1 * c - x2 * s) * SCALE;
        const float y2 = (x2 * c + x1 * s) * SCALE;
        const size_t o = (size_t)t * (NH * HD) + head * HD + j;
        __nv_bfloat16 h1 = __float2bfloat16(y1), h2 = __float2bfloat16(y2);
        qh[o] = h1;      ql[o]      = __float2bfloat16(y1 - __bfloat162float(h1));
        qh[o + 64] = h2; ql[o + 64] = __float2bfloat16(y2 - __bfloat162float(h2));
    }
    // k heads: 4 * 64 pairs
#pragma unroll
    for (int it = 0; it < 2; it++) {
        const int item = it * 128 + tid;
        const int head = item >> 6, j = item & 63;
        const float invf = powf(10000.0f, -((float)j) * (1.0f / 64.0f));
        float s, c; sincosf(p * invf, &s, &c);
        const float x1 = base[NH * HD + head * HD + j];
        const float x2 = base[NH * HD + head * HD + j + 64];
        const float y1 = x1 * c - x2 * s;
        const float y2 = x2 * c + x1 * s;
        const size_t o = (size_t)t * (NKV * HD) + head * HD + j;
        __nv_bfloat16 h1 = __float2bfloat16(y1), h2 = __float2bfloat16(y2);
        kh[o] = h1;      kl[o]      = __float2bfloat16(y1 - __bfloat162float(h1));
        kh[o + 64] = h2; kl[o + 64] = __float2bfloat16(y2 - __bfloat162float(h2));
    }
    // v: 512 values
#pragma unroll
    for (int it = 0; it < 4; it++) {
        const int idx = it * 128 + tid;
        const float x = base[(NH + NKV) * HD + idx];
        const size_t o = (size_t)t * (NKV * HD) + idx;
        __nv_bfloat16 h = __float2bfloat16(x);
        vh[o] = h; vl[o] = __float2bfloat16(x - __bfloat162float(h));
    }
}

// ---------------------------------------------------------------------------
// Tensor-core flash attention, bf16x3. BQ=BK=64, D=128.
// 128 threads (4 warps); warp w owns S/O rows 16w..16w+15.
// ---------------------------------------------------------------------------
#define PITCH 136                      // bf16 elems per smem row
#define PITCHB (PITCH * 2)             // bytes
#define AT_SMEM (4 * 64 * PITCH * 2)   // 69632 bytes

__global__ __launch_bounds__(128) void attn_mma_kernel(
    const __nv_bfloat16* __restrict__ qh, const __nv_bfloat16* __restrict__ ql,
    const __nv_bfloat16* __restrict__ kh, const __nv_bfloat16* __restrict__ kl,
    const __nv_bfloat16* __restrict__ vh, const __nv_bfloat16* __restrict__ vl,
    __nv_bfloat16* __restrict__ ctxh, __nv_bfloat16* __restrict__ ctxl)
{
    extern __shared__ __nv_bfloat16 sm[];
    __nv_bfloat16* Kh = sm;                 // doubles as Q-hi staging
    __nv_bfloat16* Kl = sm + 64 * PITCH;    // doubles as Q-lo staging
    __nv_bfloat16* Vh = sm + 2 * 64 * PITCH;
    __nv_bfloat16* Vl = sm + 3 * 64 * PITCH;

    const int tid  = threadIdx.x;
    const int lane = tid & 31;
    const int w    = tid >> 5;
    const int gr   = lane >> 2;
    const int tq   = lane & 3;
    const int qb   = (int)gridDim.x - 1 - (int)blockIdx.x;
    const int h    = blockIdx.y;
    const int kvh  = h >> 2;
    const int q0   = qb * 64;

    // ldmatrix lane byte-offset within a tile: matrix m = lane>>3, r = lane&7
    const int lm = lane >> 3;
    const int laneoff = (((lm & 1) << 3) + (lane & 7)) * PITCHB + ((lm >> 1) << 3) * 2;

    const uint32_t sKh = (uint32_t)__cvta_generic_to_shared(Kh);
    const uint32_t sKl = (uint32_t)__cvta_generic_to_shared(Kl);
    const uint32_t sVh = (uint32_t)__cvta_generic_to_shared(Vh);
    const uint32_t sVl = (uint32_t)__cvta_generic_to_shared(Vl);

    // ---- stage Q tile (hi into Kh, lo into Kl), then grab A-fragments ----
#pragma unroll
    for (int it = 0; it < 8; it++) {
        const int idx = it * 128 + tid;       // 1024 uint4 chunks
        const int row = idx >> 4;
        const int cc  = (idx & 15) * 8;       // bf16 units
        const size_t gs = (size_t)(q0 + row) * (NH * HD) + h * HD + cc;
        *(uint4*)&Kh[row * PITCH + cc] = *(const uint4*)&qh[gs];
        *(uint4*)&Kl[row * PITCH + cc] = *(const uint4*)&ql[gs];
    }
    __syncthreads();

    uint32_t qfh[8][4], qfl[8][4];
#pragma unroll
    for (int ks = 0; ks < 8; ks++) {
        const uint32_t a0 = sKh + (16 * w) * PITCHB + (16 * ks) * 2 + laneoff;
        LDSM_X4(qfh[ks][0], qfh[ks][1], qfh[ks][2], qfh[ks][3], a0);
        const uint32_t a1 = sKl + (16 * w) * PITCHB + (16 * ks) * 2 + laneoff;
        LDSM_X4(qfl[ks][0], qfl[ks][1], qfl[ks][2], qfl[ks][3], a1);
    }

    float o[16][4];
#pragma unroll
    for (int i = 0; i < 16; i++)
#pragma unroll
        for (int e = 0; e < 4; e++) o[i][e] = 0.0f;
    float mrun0 = -1e30f, mrun1 = -1e30f, lrun0 = 0.0f, lrun1 = 0.0f;

    for (int kb = 0; kb <= qb; kb++) {
        const int k0 = kb * 64;
        __syncthreads();   // protect prior smem reads (and Q staging on iter 0)

#pragma unroll
        for (int it = 0; it < 8; it++) {
            const int idx = it * 128 + tid;
            const int row = idx >> 4;
            const int cc  = (idx & 15) * 8;
            const size_t gs = (size_t)(k0 + row) * (NKV * HD) + kvh * HD + cc;
            const int ss = row * PITCH + cc;
            *(uint4*)&Kh[ss] = *(const uint4*)&kh[gs];
            *(uint4*)&Kl[ss] = *(const uint4*)&kl[gs];
            *(uint4*)&Vh[ss] = *(const uint4*)&vh[gs];
            *(uint4*)&Vl[ss] = *(const uint4*)&vl[gs];
        }
        __syncthreads();

        // ---- S = Q @ K^T (bf16x3) ----
        float s[8][4];
#pragma unroll
        for (int i = 0; i < 8; i++)
#pragma unroll
            for (int e = 0; e < 4; e++) s[i][e] = 0.0f;

#pragma unroll
        for (int nt2 = 0; nt2 < 4; nt2++) {
#pragma unroll
            for (int ks = 0; ks < 8; ks++) {
                const int toff = (16 * nt2) * PITCHB + (16 * ks) * 2 + laneoff;
                uint32_t kh0, kh1, kh2, kh3, kl0, kl1, kl2, kl3;
                LDSM_X4(kh0, kh1, kh2, kh3, sKh + toff);
                LDSM_X4(kl0, kl1, kl2, kl3, sKl + toff);
                MMA4(s[2 * nt2],     qfh[ks], kh0, kh2);
                MMA4(s[2 * nt2],     qfh[ks], kl0, kl2);
                MMA4(s[2 * nt2],     qfl[ks], kh0, kh2);
                MMA4(s[2 * nt2 + 1], qfh[ks], kh1, kh3);
                MMA4(s[2 * nt2 + 1], qfh[ks], kl1, kl3);
                MMA4(s[2 * nt2 + 1], qfl[ks], kh1, kh3);
            }
        }

        // ---- causal mask (diagonal block only) ----
        if (kb == qb) {
            const int lr0 = 16 * w + gr;
#pragma unroll
            for (int nt = 0; nt < 8; nt++) {
                const int c0 = 8 * nt + 2 * tq;
                if (c0     > lr0)     s[nt][0] = -1e30f;
                if (c0 + 1 > lr0)     s[nt][1] = -1e30f;
                if (c0     > lr0 + 8) s[nt][2] = -1e30f;
                if (c0 + 1 > lr0 + 8) s[nt][3] = -1e30f;
            }
        }

        // ---- online softmax (rows gr and gr+8; reduce over 4 tq lanes) ----
        float m0l = -1e30f, m1l = -1e30f;
#pragma unroll
        for (int nt = 0; nt < 8; nt++) {
            m0l = fmaxf(m0l, fmaxf(s[nt][0], s[nt][1]));
            m1l = fmaxf(m1l, fmaxf(s[nt][2], s[nt][3]));
        }
        m0l = fmaxf(m0l, __shfl_xor_sync(0xffffffffu, m0l, 1));
        m0l = fmaxf(m0l, __shfl_xor_sync(0xffffffffu, m0l, 2));
        m1l = fmaxf(m1l, __shfl_xor_sync(0xffffffffu, m1l, 1));
        m1l = fmaxf(m1l, __shfl_xor_sync(0xffffffffu, m1l, 2));
        const float mn0 = fmaxf(mrun0, m0l);
        const float mn1 = fmaxf(mrun1, m1l);
        const float corr0 = __expf(mrun0 - mn0);
        const float corr1 = __expf(mrun1 - mn1);
        mrun0 = mn0; mrun1 = mn1;
        float sum0 = 0.0f, sum1 = 0.0f;
#pragma unroll
        for (int nt = 0; nt < 8; nt++) {
            s[nt][0] = __expf(s[nt][0] - mn0);
            s[nt][1] = __expf(s[nt][1] - mn0);
            s[nt][2] = __expf(s[nt][2] - mn1);
            s[nt][3] = __expf(s[nt][3] - mn1);
            sum0 += s[nt][0] + s[nt][1];
            sum1 += s[nt][2] + s[nt][3];
        }
        sum0 += __shfl_xor_sync(0xffffffffu, sum0, 1);
        sum0 += __shfl_xor_sync(0xffffffffu, sum0, 2);
        sum1 += __shfl_xor_sync(0xffffffffu, sum1, 1);
        sum1 += __shfl_xor_sync(0xffffffffu, sum1, 2);
        lrun0 = lrun0 * corr0 + sum0;
        lrun1 = lrun1 * corr1 + sum1;

#pragma unroll
        for (int nt = 0; nt < 16; nt++) {
            o[nt][0] *= corr0; o[nt][1] *= corr0;
            o[nt][2] *= corr1; o[nt][3] *= corr1;
        }

        // ---- O += P @ V (bf16x3, P split in registers) ----
#pragma unroll
        for (int kvs = 0; kvs < 4; kvs++) {
            uint32_t ph[4], pl[4];
            ph[0] = packbf(s[2 * kvs][0], s[2 * kvs][1]);
            ph[1] = packbf(s[2 * kvs][2], s[2 * kvs][3]);
            ph[2] = packbf(s[2 * kvs + 1][0], s[2 * kvs + 1][1]);
            ph[3] = packbf(s[2 * kvs + 1][2], s[2 * kvs + 1][3]);
            pl[0] = packbf(bfres(s[2 * kvs][0]), bfres(s[2 * kvs][1]));
            pl[1] = packbf(bfres(s[2 * kvs][2]), bfres(s[2 * kvs][3]));
            pl[2] = packbf(bfres(s[2 * kvs + 1][0]), bfres(s[2 * kvs + 1][1]));
            pl[3] = packbf(bfres(s[2 * kvs + 1][2]), bfres(s[2 * kvs + 1][3]));
#pragma unroll
            for (int dn2 = 0; dn2 < 8; dn2++) {
                const int toff = (16 * kvs) * PITCHB + (16 * dn2) * 2 + laneoff;
                uint32_t vh0, vh1, vh2, vh3, vl0, vl1, vl2, vl3;
                LDSM_X4_T(vh0, vh1, vh2, vh3, sVh + toff);
                LDSM_X4_T(vl0, vl1, vl2, vl3, sVl + toff);
                MMA4(o[2 * dn2],     ph, vh0, vh1);
                MMA4(o[2 * dn2],     pl, vh0, vh1);
                MMA4(o[2 * dn2],     ph, vl0, vl1);
                MMA4(o[2 * dn2 + 1], ph, vh2, vh3);
                MMA4(o[2 * dn2 + 1], pl, vh2, vh3);
                MMA4(o[2 * dn2 + 1], ph, vl2, vl3);
            }
        }
    }

    // ---- epilogue: normalize, split to bf16 hi/lo, store ----
    const float inv0 = 1.0f / lrun0;
    const float inv1 = 1.0f / lrun1;
    const int row0 = q0 + 16 * w + gr;
    const int row1 = row0 + 8;
#pragma unroll
    for (int nt = 0; nt < 16; nt++) {
        const int col = h * HD + 8 * nt + 2 * tq;
        const float f0 = o[nt][0] * inv0, f1 = o[nt][1] * inv0;
        const float f2 = o[nt][2] * inv1, f3 = o[nt][3] * inv1;
        *(uint32_t*)&ctxh[(size_t)row0 * CTX_N + col] = packbf(f0, f1);
        *(uint32_t*)&ctxl[(size_t)row0 * CTX_N + col] = packbf(bfres(f0), bfres(f1));
        *(uint32_t*)&ctxh[(size_t)row1 * CTX_N + col] = packbf(f2, f3);
        *(uint32_t*)&ctxl[(size_t)row1 * CTX_N + col] = packbf(bfres(f2), bfres(f3));
    }
}

// ---------------------------------------------------------------------------
// Launch pipeline.
// ---------------------------------------------------------------------------
extern "C" void kernel_launch(void* const* d_in, const int* in_sizes, int n_in,
                              void* d_out, int out_size)
{
    const float* hidden = (const float*)d_in[0];
    const int*   pos    = (const int*)d_in[1];
    const float* Wqkv   = (const float*)d_in[2];
    const float* Wo     = (const float*)d_in[3];
    float* out = (float*)d_out;

    float* qkv_d;
    __nv_bfloat16 *hid_hi, *hid_lo, *ctx_hi, *ctx_lo;
    __nv_bfloat16 *wqkvT_hi, *wqkvT_lo, *woT_hi, *woT_lo;
    __nv_bfloat16 *qh, *ql, *kh, *kl, *vh, *vl;
    cudaGetSymbolAddress((void**)&qkv_d, g_qkv);
    cudaGetSymbolAddress((void**)&hid_hi, g_hid_hi);
    cudaGetSymbolAddress((void**)&hid_lo, g_hid_lo);
    cudaGetSymbolAddress((void**)&ctx_hi, g_ctx_hi);
    cudaGetSymbolAddress((void**)&ctx_lo, g_ctx_lo);
    cudaGetSymbolAddress((void**)&wqkvT_hi, g_wqkvT_hi);
    cudaGetSymbolAddress((void**)&wqkvT_lo, g_wqkvT_lo);
    cudaGetSymbolAddress((void**)&woT_hi, g_woT_hi);
    cudaGetSymbolAddress((void**)&woT_lo, g_woT_lo);
    cudaGetSymbolAddress((void**)&qh, g_qh);
    cudaGetSymbolAddress((void**)&ql, g_ql);
    cudaGetSymbolAddress((void**)&kh, g_kh);
    cudaGetSymbolAddress((void**)&kl, g_kl);
    cudaGetSymbolAddress((void**)&vh, g_vh);
    cudaGetSymbolAddress((void**)&vl, g_vl);

    cudaFuncSetAttribute(attn_mma_kernel, cudaFuncAttributeMaxDynamicSharedMemorySize,
                         AT_SMEM);

    // splits
    split_rows_kernel<<<(T_SEQ * HID_DIM) / (256 * 4), 256>>>(hidden, hid_hi, hid_lo);
    split_T_kernel<<<dim3(QKV_N / 32, HID_DIM / 32), dim3(32, 8)>>>(Wqkv, wqkvT_hi, wqkvT_lo, HID_DIM, QKV_N);
    split_T_kernel<<<dim3(HID_DIM / 32, CTX_N / 32), dim3(32, 8)>>>(Wo, woT_hi, woT_lo, CTX_N, HID_DIM);

    // 1) qkv = hidden @ Wqkv  (bf16x3 tensor-core GEMM)
    gemm_bf16x3_kernel<<<dim3(QKV_N / 128, T_SEQ / 128), 256>>>(
        hid_hi, hid_lo, wqkvT_hi, wqkvT_lo, qkv_d, T_SEQ, QKV_N, HID_DIM);

    // 2) RoPE + scale + split to bf16 hi/lo
    rope_split_kernel<<<T_SEQ, 128>>>(qkv_d, pos, qh, ql, kh, kl, vh, vl);

    // 3) causal GQA flash attention (tensor cores, bf16x3)
    attn_mma_kernel<<<dim3(T_SEQ / 64, NH), 128, AT_SMEM>>>(
        qh, ql, kh, kl, vh, vl, ctx_hi, ctx_lo);

    // 4) out = ctx @ Wo  (bf16x3 tensor-core GEMM)
    gemm_bf16x3_kernel<<<dim3(HID_DIM / 128, T_SEQ / 128), 256>>>(
        ctx_hi, ctx_lo, woT_hi, woT_lo, out, T_SEQ, HID_DIM, CTX_N);
}